// round 1
// baseline (speedup 1.0000x reference)
#include <cuda_runtime.h>
#include <cuda_bf16.h>

// YOLOv7 P3 head: B=16, A=3, NC=80, H=W=80, stride=8.
// in : [B, A*85, H, W] fp32 (channel-major)
// out: [B, A*H*W, 85] fp32 (85 contiguous per location)
// anchors: [3,2] fp32

#define YB 16
#define YA 3
#define YC 85          // 5 + 80
#define YH 80
#define YW 80
#define YHW (YH * YW)  // 6400
#define LOCS 128       // spatial locations per block
#define NCHUNK (YHW / LOCS)  // 50
#define THREADS 256

__device__ __forceinline__ float fast_sigmoid(float x) {
    return __fdividef(1.0f, 1.0f + __expf(-x));
}

__global__ __launch_bounds__(THREADS)
void yolov7_head_kernel(const float* __restrict__ in,
                        const float* __restrict__ anchors,
                        float* __restrict__ out) {
    // padded to 129 floats/row: stride % 32 == 1 -> conflict-free column access
    __shared__ float s[YC][LOCS + 1];   // 85 * 129 * 4 = 43860 B

    const int blk   = blockIdx.x;
    const int chunk = blk % NCHUNK;
    const int ba    = blk / NCHUNK;          // 0..47  (b*A + a)
    const int a     = ba % YA;
    const int hw0   = chunk * LOCS;

    const float aw = anchors[a * 2 + 0];
    const float ah = anchors[a * 2 + 1];

    const int tid = threadIdx.x;

    // ---------------- Phase 1: coalesced float4 loads + transform ----------------
    // input row for channel c: in + (ba*YC + c)*YHW + hw0, 128 floats contiguous.
    const float4* in4 = reinterpret_cast<const float4*>(
        in + (size_t)ba * YC * YHW + hw0);
    // channel row stride in float4 units:
    const int row4 = YHW / 4;  // 1600

    #pragma unroll 4
    for (int idx = tid; idx < YC * (LOCS / 4); idx += THREADS) {
        const int c  = idx >> 5;          // / (LOCS/4) = /32
        const int i4 = idx & 31;
        const float4 v = in4[c * row4 + i4];
        float vals[4] = {v.x, v.y, v.z, v.w};
        const int base_i = i4 * 4;

        if (c >= 4) {
            #pragma unroll
            for (int k = 0; k < 4; k++)
                s[c][base_i + k] = fast_sigmoid(vals[k]);
        } else if (c == 0) {
            #pragma unroll
            for (int k = 0; k < 4; k++) {
                const int hw = hw0 + base_i + k;
                const float gx = (float)(hw % YW);
                s[c][base_i + k] = (fast_sigmoid(vals[k]) + gx) * 8.0f;
            }
        } else if (c == 1) {
            #pragma unroll
            for (int k = 0; k < 4; k++) {
                const int hw = hw0 + base_i + k;
                const float gy = (float)(hw / YW);
                s[c][base_i + k] = (fast_sigmoid(vals[k]) + gy) * 8.0f;
            }
        } else {  // c == 2 or 3 : exp(clip(x,-16,16)) * anchor
            const float anc = (c == 2) ? aw : ah;
            #pragma unroll
            for (int k = 0; k < 4; k++) {
                float x = fminf(fmaxf(vals[k], -16.0f), 16.0f);
                s[c][base_i + k] = __expf(x) * anc;
            }
        }
    }

    __syncthreads();

    // ---------------- Phase 2: fully coalesced float4 stores ----------------
    // output chunk: out + (ba*YHW + hw0)*YC, length 128*85 = 10880 floats (16B aligned)
    float4* out4 = reinterpret_cast<float4*>(
        out + ((size_t)ba * YHW + hw0) * YC);

    #pragma unroll 4
    for (int j = tid; j < (YC * LOCS) / 4; j += THREADS) {
        const int jj = j * 4;
        float tmp[4];
        #pragma unroll
        for (int k = 0; k < 4; k++) {
            const int e   = jj + k;
            const int loc = e / YC;
            const int c   = e - loc * YC;
            tmp[k] = s[c][loc];
        }
        out4[j] = make_float4(tmp[0], tmp[1], tmp[2], tmp[3]);
    }
}

extern "C" void kernel_launch(void* const* d_in, const int* in_sizes, int n_in,
                              void* d_out, int out_size) {
    const float* in      = (const float*)d_in[0];
    const float* anchors = (const float*)d_in[1];
    float* out           = (float*)d_out;

    const int grid = YB * YA * NCHUNK;  // 2400
    yolov7_head_kernel<<<grid, THREADS>>>(in, anchors, out);
}